// round 5
// baseline (speedup 1.0000x reference)
#include <cuda_runtime.h>
#include <cuda_bf16.h>
#include <math.h>

// ---------------- problem constants ----------------
#define DM   2048
#define NH   16
#define HD   128
#define FFD  8192
#define BBATCH 2
#define SEQ  2048
#define MT   (BBATCH*SEQ)          // 4096 token rows
#define TTT  (4194304LL)           // SEQ*SEQ

// ---------------- scratch (static __device__, no allocation) ----------------
static __device__ float g_xn1 [MT*DM];
static __device__ float g_q   [MT*DM];
static __device__ float g_k   [MT*DM];
static __device__ float g_v   [MT*DM];
static __device__ float g_s   [134217728];   // B*H*SEQ*SEQ scores; softmax in place
static __device__ float g_att [MT*DM];
static __device__ float g_x1  [MT*DM];
static __device__ float g_xn2 [MT*DM];
static __device__ float g_gate[MT*FFD];
static __device__ float g_h   [MT*FFD];

// ---------------- GEMM config ----------------
constexpr int BM = 128, BN = 128, BK = 32;
constexpr int SA  = BK + 4;    // padded A/B (K-major) row stride (floats)
constexpr int SBT = BN + 4;    // padded B (natural case) row stride
constexpr int SMEM_FLOATS = 2*BM*SA + 2*BM*SA;   // covers both layouts
#define SMEM_BYTES (SMEM_FLOATS * 4)

__device__ __forceinline__ unsigned f2tf32(float x) {
    unsigned u;
    asm("cvt.rna.tf32.f32 %0, %1;" : "=r"(u) : "f"(x));
    return u;
}

__device__ __forceinline__ void mma8(float* c, const unsigned* a, const unsigned* b) {
    asm volatile(
        "mma.sync.aligned.m16n8k8.row.col.f32.tf32.tf32.f32 "
        "{%0,%1,%2,%3},{%4,%5,%6,%7},{%8,%9},{%0,%1,%2,%3};"
        : "+f"(c[0]), "+f"(c[1]), "+f"(c[2]), "+f"(c[3])
        : "r"(a[0]), "r"(a[1]), "r"(a[2]), "r"(a[3]), "r"(b[0]), "r"(b[1]));
}

#define CP16(s, g) asm volatile("cp.async.cg.shared.global [%0], [%1], 16;" :: "r"(s), "l"(g) : "memory")

// C = A @ op(B).  TB=0: B is [N,K] row-major (weights / K-major) -> C = A @ B^T
//                 TB=1: B is [K,N] row-major (V) -> C = A @ B
// EPI: 0 = plain f32 store, 1 = residual add (X), 2 = GLU: C = silu(X)*acc,
//      3 = scale by 1/sqrt(HD)
template<int TB, int EPI>
__global__ void __launch_bounds__(256, 2) gemm_k(
    const float* __restrict__ A, const float* __restrict__ B,
    float* __restrict__ C, const float* __restrict__ X,
    int M, int N, int K, int lda, int ldb, int ldc,
    long long sA1, long long sA2, long long sB1, long long sB2,
    long long sC1, long long sC2, int zdiv)
{
    extern __shared__ float sm[];
    float* As = sm;
    float* Bs = sm + 2*BM*SA;

    const int tid = threadIdx.x;
    const int z = blockIdx.z;
    const long long zq = z / zdiv, zr = z % zdiv;
    A += zq*sA1 + zr*sA2 + (long long)blockIdx.y * BM * lda;
    if (TB == 0) B += zq*sB1 + zr*sB2 + (long long)blockIdx.x * BN * ldb;
    else         B += zq*sB1 + zr*sB2 + (long long)blockIdx.x * BN;
    C += zq*sC1 + zr*sC2;
    if (EPI == 1 || EPI == 2) X += zq*sC1 + zr*sC2;

    const int KT = K / BK;

    auto load_stage = [&](int st, int kt) {
        {   // A tile: 128 rows x 32 floats
            int r = tid >> 3, c = (tid & 7) << 2;
            const float* g = A + (long long)r * lda + kt*BK + c;
            float* s = As + st*BM*SA + r*SA + c;
            #pragma unroll
            for (int p = 0; p < 4; p++) {
                unsigned sa = (unsigned)__cvta_generic_to_shared(s);
                CP16(sa, g);
                g += 32LL * lda; s += 32*SA;
            }
        }
        if (TB == 0) {   // B tile [BN][BK]
            int r = tid >> 3, c = (tid & 7) << 2;
            const float* g = B + (long long)r * ldb + kt*BK + c;
            float* s = Bs + st*BM*SA + r*SA + c;
            #pragma unroll
            for (int p = 0; p < 4; p++) {
                unsigned sa = (unsigned)__cvta_generic_to_shared(s);
                CP16(sa, g);
                g += 32LL * ldb; s += 32*SA;
            }
        } else {         // B tile natural [BK][BN]
            int r = tid >> 5, c = (tid & 31) << 2;
            const float* g = B + (long long)(kt*BK + r) * ldb + c;
            float* s = Bs + st*BK*SBT + r*SBT + c;
            #pragma unroll
            for (int p = 0; p < 4; p++) {
                unsigned sa = (unsigned)__cvta_generic_to_shared(s);
                CP16(sa, g);
                g += 8LL * ldb; s += 8*SBT;
            }
        }
    };

    float acc[4][4][4];
    #pragma unroll
    for (int i = 0; i < 4; i++)
        #pragma unroll
        for (int j = 0; j < 4; j++)
            #pragma unroll
            for (int l = 0; l < 4; l++) acc[i][j][l] = 0.f;

    const int lane = tid & 31, wid = tid >> 5;
    const int gr = lane >> 2, tg = lane & 3;
    const int wm = wid >> 2, wn = wid & 3;   // 2 x 4 warp grid, warp tile 64x32

    load_stage(0, 0);
    asm volatile("cp.async.commit_group;" ::: "memory");

    for (int kt = 0; kt < KT; kt++) {
        if (kt + 1 < KT) load_stage((kt + 1) & 1, kt + 1);
        asm volatile("cp.async.commit_group;" ::: "memory");
        asm volatile("cp.async.wait_group 1;" ::: "memory");
        __syncthreads();

        const float* Ab  = As + (kt & 1) * BM * SA + (wm*64 + gr) * SA;
        const float* Bb0 = Bs + (kt & 1) * (TB ? BK*SBT : BM*SA);

        #pragma unroll
        for (int ks = 0; ks < BK/8; ks++) {
            const int kk = ks * 8;
            unsigned af[4][4];
            #pragma unroll
            for (int mt = 0; mt < 4; mt++) {
                const float* p = Ab + mt*16*SA + kk + tg;
                af[mt][0] = f2tf32(p[0]);
                af[mt][1] = f2tf32(p[8*SA]);
                af[mt][2] = f2tf32(p[4]);
                af[mt][3] = f2tf32(p[8*SA + 4]);
            }
            unsigned bf[4][2];
            #pragma unroll
            for (int nt = 0; nt < 4; nt++) {
                if (TB == 0) {
                    const float* p = Bb0 + (wn*32 + nt*8 + gr)*SA + kk + tg;
                    bf[nt][0] = f2tf32(p[0]);
                    bf[nt][1] = f2tf32(p[4]);
                } else {
                    const float* p = Bb0 + (kk + tg)*SBT + wn*32 + nt*8 + gr;
                    bf[nt][0] = f2tf32(p[0]);
                    bf[nt][1] = f2tf32(p[4*SBT]);
                }
            }
            #pragma unroll
            for (int mt = 0; mt < 4; mt++)
                #pragma unroll
                for (int nt = 0; nt < 4; nt++)
                    mma8(acc[mt][nt], af[mt], bf[nt]);
        }
        __syncthreads();
    }

    // epilogue
    const float SC = 0.08838834764831845f;   // 1/sqrt(128)
    #pragma unroll
    for (int mt = 0; mt < 4; mt++) {
        #pragma unroll
        for (int nt = 0; nt < 4; nt++) {
            int row = blockIdx.y*BM + wm*64 + mt*16 + gr;
            int col = blockIdx.x*BN + wn*32 + nt*8 + tg*2;
            #pragma unroll
            for (int hh = 0; hh < 2; hh++) {
                long long idx = (long long)(row + hh*8) * ldc + col;
                float2 vv = make_float2(acc[mt][nt][hh*2], acc[mt][nt][hh*2+1]);
                if (EPI == 1) {
                    float2 r = *(const float2*)(X + idx);
                    vv.x += r.x; vv.y += r.y;
                }
                if (EPI == 2) {
                    float2 gg = *(const float2*)(X + idx);
                    vv.x *= gg.x / (1.f + __expf(-gg.x));
                    vv.y *= gg.y / (1.f + __expf(-gg.y));
                }
                if (EPI == 3) { vv.x *= SC; vv.y *= SC; }
                *(float2*)(C + idx) = vv;
            }
        }
    }
}

// ---------------- LayerNorm: one block per row of 2048 ----------------
__global__ void ln_kernel(const float* __restrict__ x, const float* __restrict__ w,
                          const float* __restrict__ b, float* __restrict__ o)
{
    __shared__ float rs[8], rss[8];
    __shared__ float s_mu, s_rstd;
    long long base = (long long)blockIdx.x * DM;
    int tid = threadIdx.x;
    int c = tid * 8;
    float4 v0 = *(const float4*)(x + base + c);
    float4 v1 = *(const float4*)(x + base + c + 4);
    float s  = v0.x+v0.y+v0.z+v0.w + v1.x+v1.y+v1.z+v1.w;
    float ss = v0.x*v0.x+v0.y*v0.y+v0.z*v0.z+v0.w*v0.w
             + v1.x*v1.x+v1.y*v1.y+v1.z*v1.z+v1.w*v1.w;
    #pragma unroll
    for (int off = 16; off; off >>= 1) {
        s  += __shfl_xor_sync(0xffffffffu, s,  off);
        ss += __shfl_xor_sync(0xffffffffu, ss, off);
    }
    if ((tid & 31) == 0) { rs[tid >> 5] = s; rss[tid >> 5] = ss; }
    __syncthreads();
    if (tid == 0) {
        float S = 0.f, SS = 0.f;
        for (int i = 0; i < 8; i++) { S += rs[i]; SS += rss[i]; }
        float mu = S / DM;
        float var = SS / DM - mu * mu;
        s_mu = mu; s_rstd = rsqrtf(var + 1e-5f);
    }
    __syncthreads();
    float mu = s_mu, rstd = s_rstd;
    float4 w0 = *(const float4*)(w + c), w1 = *(const float4*)(w + c + 4);
    float4 b0 = *(const float4*)(b + c), b1 = *(const float4*)(b + c + 4);
    float4 o0, o1;
    o0.x = (v0.x-mu)*rstd*w0.x + b0.x;  o0.y = (v0.y-mu)*rstd*w0.y + b0.y;
    o0.z = (v0.z-mu)*rstd*w0.z + b0.z;  o0.w = (v0.w-mu)*rstd*w0.w + b0.w;
    o1.x = (v1.x-mu)*rstd*w1.x + b1.x;  o1.y = (v1.y-mu)*rstd*w1.y + b1.y;
    o1.z = (v1.z-mu)*rstd*w1.z + b1.z;  o1.w = (v1.w-mu)*rstd*w1.w + b1.w;
    *(float4*)(o + base + c)     = o0;
    *(float4*)(o + base + c + 4) = o1;
}

// ---------------- in-place softmax over rows of 2048 (scores pre-scaled) ----------------
__global__ void softmax_kernel(float* __restrict__ S)
{
    __shared__ float red[8];
    __shared__ float bcast;
    long long base = (long long)blockIdx.x * SEQ;
    int tid = threadIdx.x;
    int lane = tid & 31, wid = tid >> 5;
    int c = tid * 8;
    float v[8];
    float4 a = *(const float4*)(S + base + c);
    float4 b = *(const float4*)(S + base + c + 4);
    v[0]=a.x; v[1]=a.y; v[2]=a.z; v[3]=a.w;
    v[4]=b.x; v[5]=b.y; v[6]=b.z; v[7]=b.w;
    float m = v[0];
    #pragma unroll
    for (int i = 1; i < 8; i++) m = fmaxf(m, v[i]);
    #pragma unroll
    for (int off = 16; off; off >>= 1) m = fmaxf(m, __shfl_xor_sync(0xffffffffu, m, off));
    if (lane == 0) red[wid] = m;
    __syncthreads();
    if (tid == 0) {
        float mm = red[0];
        for (int i = 1; i < 8; i++) mm = fmaxf(mm, red[i]);
        bcast = mm;
    }
    __syncthreads();
    m = bcast;
    float s = 0.f;
    #pragma unroll
    for (int i = 0; i < 8; i++) { v[i] = __expf(v[i] - m); s += v[i]; }
    #pragma unroll
    for (int off = 16; off; off >>= 1) s += __shfl_xor_sync(0xffffffffu, s, off);
    __syncthreads();                 // protect red/bcast reuse
    if (lane == 0) red[wid] = s;
    __syncthreads();
    if (tid == 0) {
        float t = 0.f;
        for (int i = 0; i < 8; i++) t += red[i];
        bcast = 1.f / t;
    }
    __syncthreads();
    float inv = bcast;
    float4 o0 = make_float4(v[0]*inv, v[1]*inv, v[2]*inv, v[3]*inv);
    float4 o1 = make_float4(v[4]*inv, v[5]*inv, v[6]*inv, v[7]*inv);
    *(float4*)(S + base + c)     = o0;
    *(float4*)(S + base + c + 4) = o1;
}

// ---------------- orchestration ----------------
extern "C" void kernel_launch(void* const* d_in, const int* in_sizes, int n_in,
                              void* d_out, int out_size)
{
    const float* x   = (const float*)d_in[0];
    const float* wq  = (const float*)d_in[1];
    const float* wk  = (const float*)d_in[2];
    const float* wv  = (const float*)d_in[3];
    const float* wo  = (const float*)d_in[4];
    const float* wg  = (const float*)d_in[5];
    const float* wu  = (const float*)d_in[6];
    const float* wd  = (const float*)d_in[7];
    const float* l1w = (const float*)d_in[8];
    const float* l1b = (const float*)d_in[9];
    const float* l2w = (const float*)d_in[10];
    const float* l2b = (const float*)d_in[11];
    float* out = (float*)d_out;

    float *xn1, *q, *k, *v, *s, *att, *x1, *xn2, *gt, *h;
    cudaGetSymbolAddress((void**)&xn1, g_xn1);
    cudaGetSymbolAddress((void**)&q,   g_q);
    cudaGetSymbolAddress((void**)&k,   g_k);
    cudaGetSymbolAddress((void**)&v,   g_v);
    cudaGetSymbolAddress((void**)&s,   g_s);
    cudaGetSymbolAddress((void**)&att, g_att);
    cudaGetSymbolAddress((void**)&x1,  g_x1);
    cudaGetSymbolAddress((void**)&xn2, g_xn2);
    cudaGetSymbolAddress((void**)&gt,  g_gate);
    cudaGetSymbolAddress((void**)&h,   g_h);

    cudaFuncSetAttribute(gemm_k<0,0>, cudaFuncAttributeMaxDynamicSharedMemorySize, SMEM_BYTES);
    cudaFuncSetAttribute(gemm_k<0,1>, cudaFuncAttributeMaxDynamicSharedMemorySize, SMEM_BYTES);
    cudaFuncSetAttribute(gemm_k<0,2>, cudaFuncAttributeMaxDynamicSharedMemorySize, SMEM_BYTES);
    cudaFuncSetAttribute(gemm_k<0,3>, cudaFuncAttributeMaxDynamicSharedMemorySize, SMEM_BYTES);
    cudaFuncSetAttribute(gemm_k<1,0>, cudaFuncAttributeMaxDynamicSharedMemorySize, SMEM_BYTES);

    const long long TD = (long long)SEQ * DM;   // per-batch stride in q/k/v/att

    // LN1
    ln_kernel<<<MT, 256>>>(x, l1w, l1b, xn1);

    // Q, K, V projections: [4096,2048] @ W^T
    dim3 gq(DM/BN, MT/BM, 1);
    gemm_k<0,0><<<gq, 256, SMEM_BYTES>>>(xn1, wq, q, nullptr, MT, DM, DM, DM, DM, DM,
                                         0,0,0,0,0,0, 1);
    gemm_k<0,0><<<gq, 256, SMEM_BYTES>>>(xn1, wk, k, nullptr, MT, DM, DM, DM, DM, DM,
                                         0,0,0,0,0,0, 1);
    gemm_k<0,0><<<gq, 256, SMEM_BYTES>>>(xn1, wv, v, nullptr, MT, DM, DM, DM, DM, DM,
                                         0,0,0,0,0,0, 1);

    // scores: per (b,h): S = (Q_h @ K_h^T) / sqrt(HD)   [2048 x 2048 x 128]
    dim3 gs(SEQ/BN, SEQ/BM, BBATCH*NH);
    gemm_k<0,3><<<gs, 256, SMEM_BYTES>>>(q, k, s, nullptr, SEQ, SEQ, HD, DM, DM, SEQ,
                                         TD, HD, TD, HD, (long long)NH*TTT, TTT, NH);

    // softmax rows, in place
    softmax_kernel<<<BBATCH*NH*SEQ, 256>>>(s);

    // attn out: per (b,h): O = P @ V_h   [2048 x 128 x 2048], B natural [K,N]
    dim3 gpv(HD/BN, SEQ/BM, BBATCH*NH);
    gemm_k<1,0><<<gpv, 256, SMEM_BYTES>>>(s, v, att, nullptr, SEQ, HD, SEQ, SEQ, DM, DM,
                                          (long long)NH*TTT, TTT, TD, HD, TD, HD, NH);

    // O projection + residual: x1 = x + att @ wo^T
    gemm_k<0,1><<<gq, 256, SMEM_BYTES>>>(att, wo, x1, x, MT, DM, DM, DM, DM, DM,
                                         0,0,0,0,0,0, 1);

    // LN2
    ln_kernel<<<MT, 256>>>(x1, l2w, l2b, xn2);

    // gate = xn2 @ wg^T ; h = silu(gate) * (xn2 @ wu^T)
    dim3 gff(FFD/BN, MT/BM, 1);
    gemm_k<0,0><<<gff, 256, SMEM_BYTES>>>(xn2, wg, gt, nullptr, MT, FFD, DM, DM, DM, FFD,
                                          0,0,0,0,0,0, 1);
    gemm_k<0,2><<<gff, 256, SMEM_BYTES>>>(xn2, wu, h, gt, MT, FFD, DM, DM, DM, FFD,
                                          0,0,0,0,0,0, 1);

    // out = x1 + h @ wd^T
    dim3 gd(DM/BN, MT/BM, 1);
    gemm_k<0,1><<<gd, 256, SMEM_BYTES>>>(h, wd, out, x1, MT, DM, FFD, FFD, FFD, DM,
                                         0,0,0,0,0,0, 1);
}

// round 6
// speedup vs baseline: 1.0479x; 1.0479x over previous
#include <cuda_runtime.h>
#include <cuda_bf16.h>
#include <math.h>

// ---------------- problem constants ----------------
#define DM   2048
#define NH   16
#define HD   128
#define FFD  8192
#define BBATCH 2
#define SEQ  2048
#define MT   (BBATCH*SEQ)          // 4096 token rows
#define TTT  (4194304LL)           // SEQ*SEQ

// ---------------- scratch (static __device__, no allocation) ----------------
static __device__ float g_xn1 [MT*DM];
static __device__ float g_q   [MT*DM];
static __device__ float g_k   [MT*DM];
static __device__ float g_v   [MT*DM];
static __device__ float g_s   [134217728];   // B*H*SEQ*SEQ scores; softmax in place
static __device__ float g_att [MT*DM];
static __device__ float g_x1  [MT*DM];
static __device__ float g_xn2 [MT*DM];
static __device__ float g_gate[MT*FFD];
static __device__ float g_h   [MT*FFD];
// pre-rounded (tf32-valued) weights
static __device__ float g_wq [DM*DM];
static __device__ float g_wk [DM*DM];
static __device__ float g_wv [DM*DM];
static __device__ float g_wo [DM*DM];
static __device__ float g_wg [FFD*DM];
static __device__ float g_wu [FFD*DM];
static __device__ float g_wd [DM*FFD];

// ---------------- GEMM config ----------------
constexpr int BM = 128, BN = 128, BK = 32;
constexpr int SA  = BK + 4;    // padded A/B (K-major) row stride (floats)
constexpr int SBT = BN + 4;    // padded B (natural case) row stride
constexpr int SMEM_FLOATS = 2*BM*SA + 2*BM*SA;   // covers both layouts
#define SMEM_BYTES (SMEM_FLOATS * 4)

__device__ __forceinline__ float rnd_tf32(float x) {
    unsigned u;
    asm("cvt.rna.tf32.f32 %0, %1;" : "=r"(u) : "f"(x));
    return __uint_as_float(u);
}

__device__ __forceinline__ void mma8(float* c, const unsigned* a, const unsigned* b) {
    asm volatile(
        "mma.sync.aligned.m16n8k8.row.col.f32.tf32.tf32.f32 "
        "{%0,%1,%2,%3},{%4,%5,%6,%7},{%8,%9},{%0,%1,%2,%3};"
        : "+f"(c[0]), "+f"(c[1]), "+f"(c[2]), "+f"(c[3])
        : "r"(a[0]), "r"(a[1]), "r"(a[2]), "r"(a[3]), "r"(b[0]), "r"(b[1]));
}

#define CP16(s, g) asm volatile("cp.async.cg.shared.global [%0], [%1], 16;" :: "r"(s), "l"(g) : "memory")

// C = A @ op(B).  TB=0: B is [N,K] row-major -> C = A @ B^T
//                 TB=1: B is [K,N] row-major -> C = A @ B
// All A/B inputs MUST already be tf32-rounded (raw-bit feed into mma).
// EPI: 0 = plain f32 store, 1 = residual add (X), 2 = GLU rounded store,
//      3 = scale by 1/sqrt(HD), 4 = tf32-rounded store
template<int TB, int EPI>
__global__ void __launch_bounds__(256, 2) gemm_k(
    const float* __restrict__ A, const float* __restrict__ B,
    float* __restrict__ C, const float* __restrict__ X,
    int M, int N, int K, int lda, int ldb, int ldc,
    long long sA1, long long sA2, long long sB1, long long sB2,
    long long sC1, long long sC2, int zdiv)
{
    extern __shared__ float sm[];
    float* As = sm;
    float* Bs = sm + 2*BM*SA;

    const int tid = threadIdx.x;
    const int z = blockIdx.z;
    const long long zq = z / zdiv, zr = z % zdiv;
    A += zq*sA1 + zr*sA2 + (long long)blockIdx.y * BM * lda;
    if (TB == 0) B += zq*sB1 + zr*sB2 + (long long)blockIdx.x * BN * ldb;
    else         B += zq*sB1 + zr*sB2 + (long long)blockIdx.x * BN;
    C += zq*sC1 + zr*sC2;
    if (EPI == 1 || EPI == 2) X += zq*sC1 + zr*sC2;

    const int KT = K / BK;

    auto load_stage = [&](int st, int kt) {
        {   // A tile: 128 rows x 32 floats
            int r = tid >> 3, c = (tid & 7) << 2;
            const float* g = A + (long long)r * lda + kt*BK + c;
            float* s = As + st*BM*SA + r*SA + c;
            #pragma unroll
            for (int p = 0; p < 4; p++) {
                unsigned sa = (unsigned)__cvta_generic_to_shared(s);
                CP16(sa, g);
                g += 32LL * lda; s += 32*SA;
            }
        }
        if (TB == 0) {   // B tile [BN][BK]
            int r = tid >> 3, c = (tid & 7) << 2;
            const float* g = B + (long long)r * ldb + kt*BK + c;
            float* s = Bs + st*BM*SA + r*SA + c;
            #pragma unroll
            for (int p = 0; p < 4; p++) {
                unsigned sa = (unsigned)__cvta_generic_to_shared(s);
                CP16(sa, g);
                g += 32LL * ldb; s += 32*SA;
            }
        } else {         // B tile natural [BK][BN]
            int r = tid >> 5, c = (tid & 31) << 2;
            const float* g = B + (long long)(kt*BK + r) * ldb + c;
            float* s = Bs + st*BK*SBT + r*SBT + c;
            #pragma unroll
            for (int p = 0; p < 4; p++) {
                unsigned sa = (unsigned)__cvta_generic_to_shared(s);
                CP16(sa, g);
                g += 8LL * ldb; s += 8*SBT;
            }
        }
    };

    float acc[4][4][4];
    #pragma unroll
    for (int i = 0; i < 4; i++)
        #pragma unroll
        for (int j = 0; j < 4; j++)
            #pragma unroll
            for (int l = 0; l < 4; l++) acc[i][j][l] = 0.f;

    const int lane = tid & 31, wid = tid >> 5;
    const int gr = lane >> 2, tg = lane & 3;
    const int wm = wid >> 2, wn = wid & 3;   // 2 x 4 warp grid, warp tile 64x32

    load_stage(0, 0);
    asm volatile("cp.async.commit_group;" ::: "memory");

    for (int kt = 0; kt < KT; kt++) {
        if (kt + 1 < KT) load_stage((kt + 1) & 1, kt + 1);
        asm volatile("cp.async.commit_group;" ::: "memory");
        asm volatile("cp.async.wait_group 1;" ::: "memory");
        __syncthreads();

        const float* Ab  = As + (kt & 1) * BM * SA + (wm*64 + gr) * SA;
        const float* Bb0 = Bs + (kt & 1) * (TB ? BK*SBT : BM*SA);

        #pragma unroll
        for (int ks = 0; ks < BK/8; ks++) {
            const int kk = ks * 8;
            unsigned af[4][4];
            #pragma unroll
            for (int mt = 0; mt < 4; mt++) {
                const float* p = Ab + mt*16*SA + kk + tg;
                af[mt][0] = __float_as_uint(p[0]);
                af[mt][1] = __float_as_uint(p[8*SA]);
                af[mt][2] = __float_as_uint(p[4]);
                af[mt][3] = __float_as_uint(p[8*SA + 4]);
            }
            unsigned bf[4][2];
            #pragma unroll
            for (int nt = 0; nt < 4; nt++) {
                if (TB == 0) {
                    const float* p = Bb0 + (wn*32 + nt*8 + gr)*SA + kk + tg;
                    bf[nt][0] = __float_as_uint(p[0]);
                    bf[nt][1] = __float_as_uint(p[4]);
                } else {
                    const float* p = Bb0 + (kk + tg)*SBT + wn*32 + nt*8 + gr;
                    bf[nt][0] = __float_as_uint(p[0]);
                    bf[nt][1] = __float_as_uint(p[4*SBT]);
                }
            }
            #pragma unroll
            for (int mt = 0; mt < 4; mt++)
                #pragma unroll
                for (int nt = 0; nt < 4; nt++)
                    mma8(acc[mt][nt], af[mt], bf[nt]);
        }
        __syncthreads();
    }

    // epilogue
    const float SC = 0.08838834764831845f;   // 1/sqrt(128)
    #pragma unroll
    for (int mt = 0; mt < 4; mt++) {
        #pragma unroll
        for (int nt = 0; nt < 4; nt++) {
            int row = blockIdx.y*BM + wm*64 + mt*16 + gr;
            int col = blockIdx.x*BN + wn*32 + nt*8 + tg*2;
            #pragma unroll
            for (int hh = 0; hh < 2; hh++) {
                long long idx = (long long)(row + hh*8) * ldc + col;
                float2 vv = make_float2(acc[mt][nt][hh*2], acc[mt][nt][hh*2+1]);
                if (EPI == 1) {
                    float2 r = *(const float2*)(X + idx);
                    vv.x += r.x; vv.y += r.y;
                }
                if (EPI == 2) {
                    float2 gg = *(const float2*)(X + idx);
                    vv.x *= gg.x / (1.f + __expf(-gg.x));
                    vv.y *= gg.y / (1.f + __expf(-gg.y));
                    vv.x = rnd_tf32(vv.x); vv.y = rnd_tf32(vv.y);   // h feeds down-proj
                }
                if (EPI == 3) { vv.x *= SC; vv.y *= SC; }
                if (EPI == 4) { vv.x = rnd_tf32(vv.x); vv.y = rnd_tf32(vv.y); }
                *(float2*)(C + idx) = vv;
            }
        }
    }
}

// ---------------- weight pre-rounding to tf32 values ----------------
__global__ void round_kernel(const float* __restrict__ in, float* __restrict__ out)
{
    long long i = ((long long)blockIdx.x * 256 + threadIdx.x) * 4;
    float4 v = *(const float4*)(in + i);
    v.x = rnd_tf32(v.x); v.y = rnd_tf32(v.y);
    v.z = rnd_tf32(v.z); v.w = rnd_tf32(v.w);
    *(float4*)(out + i) = v;
}

// ---------------- LayerNorm: one block per row of 2048 (tf32-rounded output) ----------------
__global__ void ln_kernel(const float* __restrict__ x, const float* __restrict__ w,
                          const float* __restrict__ b, float* __restrict__ o)
{
    __shared__ float rs[8], rss[8];
    __shared__ float s_mu, s_rstd;
    long long base = (long long)blockIdx.x * DM;
    int tid = threadIdx.x;
    int c = tid * 8;
    float4 v0 = *(const float4*)(x + base + c);
    float4 v1 = *(const float4*)(x + base + c + 4);
    float s  = v0.x+v0.y+v0.z+v0.w + v1.x+v1.y+v1.z+v1.w;
    float ss = v0.x*v0.x+v0.y*v0.y+v0.z*v0.z+v0.w*v0.w
             + v1.x*v1.x+v1.y*v1.y+v1.z*v1.z+v1.w*v1.w;
    #pragma unroll
    for (int off = 16; off; off >>= 1) {
        s  += __shfl_xor_sync(0xffffffffu, s,  off);
        ss += __shfl_xor_sync(0xffffffffu, ss, off);
    }
    if ((tid & 31) == 0) { rs[tid >> 5] = s; rss[tid >> 5] = ss; }
    __syncthreads();
    if (tid == 0) {
        float S = 0.f, SS = 0.f;
        for (int i = 0; i < 8; i++) { S += rs[i]; SS += rss[i]; }
        float mu = S / DM;
        float var = SS / DM - mu * mu;
        s_mu = mu; s_rstd = rsqrtf(var + 1e-5f);
    }
    __syncthreads();
    float mu = s_mu, rstd = s_rstd;
    float4 w0 = *(const float4*)(w + c), w1 = *(const float4*)(w + c + 4);
    float4 b0 = *(const float4*)(b + c), b1 = *(const float4*)(b + c + 4);
    float4 o0, o1;
    o0.x = rnd_tf32((v0.x-mu)*rstd*w0.x + b0.x);  o0.y = rnd_tf32((v0.y-mu)*rstd*w0.y + b0.y);
    o0.z = rnd_tf32((v0.z-mu)*rstd*w0.z + b0.z);  o0.w = rnd_tf32((v0.w-mu)*rstd*w0.w + b0.w);
    o1.x = rnd_tf32((v1.x-mu)*rstd*w1.x + b1.x);  o1.y = rnd_tf32((v1.y-mu)*rstd*w1.y + b1.y);
    o1.z = rnd_tf32((v1.z-mu)*rstd*w1.z + b1.z);  o1.w = rnd_tf32((v1.w-mu)*rstd*w1.w + b1.w);
    *(float4*)(o + base + c)     = o0;
    *(float4*)(o + base + c + 4) = o1;
}

// ---------------- in-place softmax over rows of 2048 (tf32-rounded output) ----------------
__global__ void softmax_kernel(float* __restrict__ S)
{
    __shared__ float red[8];
    __shared__ float bcast;
    long long base = (long long)blockIdx.x * SEQ;
    int tid = threadIdx.x;
    int lane = tid & 31, wid = tid >> 5;
    int c = tid * 8;
    float v[8];
    float4 a = *(const float4*)(S + base + c);
    float4 b = *(const float4*)(S + base + c + 4);
    v[0]=a.x; v[1]=a.y; v[2]=a.z; v[3]=a.w;
    v[4]=b.x; v[5]=b.y; v[6]=b.z; v[7]=b.w;
    float m = v[0];
    #pragma unroll
    for (int i = 1; i < 8; i++) m = fmaxf(m, v[i]);
    #pragma unroll
    for (int off = 16; off; off >>= 1) m = fmaxf(m, __shfl_xor_sync(0xffffffffu, m, off));
    if (lane == 0) red[wid] = m;
    __syncthreads();
    if (tid == 0) {
        float mm = red[0];
        for (int i = 1; i < 8; i++) mm = fmaxf(mm, red[i]);
        bcast = mm;
    }
    __syncthreads();
    m = bcast;
    float s = 0.f;
    #pragma unroll
    for (int i = 0; i < 8; i++) { v[i] = __expf(v[i] - m); s += v[i]; }
    #pragma unroll
    for (int off = 16; off; off >>= 1) s += __shfl_xor_sync(0xffffffffu, s, off);
    __syncthreads();                 // protect red/bcast reuse
    if (lane == 0) red[wid] = s;
    __syncthreads();
    if (tid == 0) {
        float t = 0.f;
        for (int i = 0; i < 8; i++) t += red[i];
        bcast = 1.f / t;
    }
    __syncthreads();
    float inv = bcast;
    float4 o0 = make_float4(rnd_tf32(v[0]*inv), rnd_tf32(v[1]*inv),
                            rnd_tf32(v[2]*inv), rnd_tf32(v[3]*inv));
    float4 o1 = make_float4(rnd_tf32(v[4]*inv), rnd_tf32(v[5]*inv),
                            rnd_tf32(v[6]*inv), rnd_tf32(v[7]*inv));
    *(float4*)(S + base + c)     = o0;
    *(float4*)(S + base + c + 4) = o1;
}

// ---------------- orchestration ----------------
extern "C" void kernel_launch(void* const* d_in, const int* in_sizes, int n_in,
                              void* d_out, int out_size)
{
    const float* x   = (const float*)d_in[0];
    const float* wq  = (const float*)d_in[1];
    const float* wk  = (const float*)d_in[2];
    const float* wv  = (const float*)d_in[3];
    const float* wo  = (const float*)d_in[4];
    const float* wg  = (const float*)d_in[5];
    const float* wu  = (const float*)d_in[6];
    const float* wd  = (const float*)d_in[7];
    const float* l1w = (const float*)d_in[8];
    const float* l1b = (const float*)d_in[9];
    const float* l2w = (const float*)d_in[10];
    const float* l2b = (const float*)d_in[11];
    float* out = (float*)d_out;

    float *xn1, *q, *k, *v, *s, *att, *x1, *xn2, *gt, *h;
    float *rwq, *rwk, *rwv, *rwo, *rwg, *rwu, *rwd;
    cudaGetSymbolAddress((void**)&xn1, g_xn1);
    cudaGetSymbolAddress((void**)&q,   g_q);
    cudaGetSymbolAddress((void**)&k,   g_k);
    cudaGetSymbolAddress((void**)&v,   g_v);
    cudaGetSymbolAddress((void**)&s,   g_s);
    cudaGetSymbolAddress((void**)&att, g_att);
    cudaGetSymbolAddress((void**)&x1,  g_x1);
    cudaGetSymbolAddress((void**)&xn2, g_xn2);
    cudaGetSymbolAddress((void**)&gt,  g_gate);
    cudaGetSymbolAddress((void**)&h,   g_h);
    cudaGetSymbolAddress((void**)&rwq, g_wq);
    cudaGetSymbolAddress((void**)&rwk, g_wk);
    cudaGetSymbolAddress((void**)&rwv, g_wv);
    cudaGetSymbolAddress((void**)&rwo, g_wo);
    cudaGetSymbolAddress((void**)&rwg, g_wg);
    cudaGetSymbolAddress((void**)&rwu, g_wu);
    cudaGetSymbolAddress((void**)&rwd, g_wd);

    cudaFuncSetAttribute(gemm_k<0,0>, cudaFuncAttributeMaxDynamicSharedMemorySize, SMEM_BYTES);
    cudaFuncSetAttribute(gemm_k<0,1>, cudaFuncAttributeMaxDynamicSharedMemorySize, SMEM_BYTES);
    cudaFuncSetAttribute(gemm_k<0,2>, cudaFuncAttributeMaxDynamicSharedMemorySize, SMEM_BYTES);
    cudaFuncSetAttribute(gemm_k<0,3>, cudaFuncAttributeMaxDynamicSharedMemorySize, SMEM_BYTES);
    cudaFuncSetAttribute(gemm_k<0,4>, cudaFuncAttributeMaxDynamicSharedMemorySize, SMEM_BYTES);
    cudaFuncSetAttribute(gemm_k<1,4>, cudaFuncAttributeMaxDynamicSharedMemorySize, SMEM_BYTES);

    const long long TD = (long long)SEQ * DM;   // per-batch stride in q/k/v/att

    // weight pre-rounding (tf32 values, raw-bit GEMM feed)
    round_kernel<<<DM*DM/1024,  256>>>(wq, rwq);
    round_kernel<<<DM*DM/1024,  256>>>(wk, rwk);
    round_kernel<<<DM*DM/1024,  256>>>(wv, rwv);
    round_kernel<<<DM*DM/1024,  256>>>(wo, rwo);
    round_kernel<<<FFD*DM/1024, 256>>>(wg, rwg);
    round_kernel<<<FFD*DM/1024, 256>>>(wu, rwu);
    round_kernel<<<DM*FFD/1024, 256>>>(wd, rwd);

    // LN1 (rounded output)
    ln_kernel<<<MT, 256>>>(x, l1w, l1b, xn1);

    // Q, K, V projections: [4096,2048] @ W^T, rounded stores
    dim3 gq(DM/BN, MT/BM, 1);
    gemm_k<0,4><<<gq, 256, SMEM_BYTES>>>(xn1, rwq, q, nullptr, MT, DM, DM, DM, DM, DM,
                                         0,0,0,0,0,0, 1);
    gemm_k<0,4><<<gq, 256, SMEM_BYTES>>>(xn1, rwk, k, nullptr, MT, DM, DM, DM, DM, DM,
                                         0,0,0,0,0,0, 1);
    gemm_k<0,4><<<gq, 256, SMEM_BYTES>>>(xn1, rwv, v, nullptr, MT, DM, DM, DM, DM, DM,
                                         0,0,0,0,0,0, 1);

    // scores: per (b,h): S = (Q_h @ K_h^T) / sqrt(HD)   [2048 x 2048 x 128]
    dim3 gs(SEQ/BN, SEQ/BM, BBATCH*NH);
    gemm_k<0,3><<<gs, 256, SMEM_BYTES>>>(q, k, s, nullptr, SEQ, SEQ, HD, DM, DM, SEQ,
                                         TD, HD, TD, HD, (long long)NH*TTT, TTT, NH);

    // softmax rows, in place, rounded output
    softmax_kernel<<<BBATCH*NH*SEQ, 256>>>(s);

    // attn out: per (b,h): O = P @ V_h   [2048 x 128 x 2048], rounded store
    dim3 gpv(HD/BN, SEQ/BM, BBATCH*NH);
    gemm_k<1,4><<<gpv, 256, SMEM_BYTES>>>(s, v, att, nullptr, SEQ, HD, SEQ, SEQ, DM, DM,
                                          (long long)NH*TTT, TTT, TD, HD, TD, HD, NH);

    // O projection + residual: x1 = x + att @ wo^T   (exact f32 store)
    gemm_k<0,1><<<gq, 256, SMEM_BYTES>>>(att, rwo, x1, x, MT, DM, DM, DM, DM, DM,
                                         0,0,0,0,0,0, 1);

    // LN2 (rounded output)
    ln_kernel<<<MT, 256>>>(x1, l2w, l2b, xn2);

    // gate = xn2 @ wg^T ; h = silu(gate) * (xn2 @ wu^T), h rounded
    dim3 gff(FFD/BN, MT/BM, 1);
    gemm_k<0,0><<<gff, 256, SMEM_BYTES>>>(xn2, rwg, gt, nullptr, MT, FFD, DM, DM, DM, FFD,
                                          0,0,0,0,0,0, 1);
    gemm_k<0,2><<<gff, 256, SMEM_BYTES>>>(xn2, rwu, h, gt, MT, FFD, DM, DM, DM, FFD,
                                          0,0,0,0,0,0, 1);

    // out = x1 + h @ wd^T   (exact f32 store)
    dim3 gd(DM/BN, MT/BM, 1);
    gemm_k<0,1><<<gd, 256, SMEM_BYTES>>>(h, rwd, out, x1, MT, DM, FFD, FFD, FFD, DM,
                                         0,0,0,0,0,0, 1);
}